// round 11
// baseline (speedup 1.0000x reference)
#include <cuda_runtime.h>
#include <cstdint>

// Encoder: out[r,0] = x[r]; out[r,1+i] = square(2*pi * x[r] * 2^i), i = 0..14
//
// Exact integer decision: with t = fl32(2pi*x) = M*2^(e-150) and
// C = fl32(2pi) = Mc*2^-21 (Mc = 13176795), sign for freq i is bit (14-i) of
//   B = floor((t/C) * 2^15) = floor(M * 2^(e-114) / Mc)
// via Granlund-Montgomery: MAGIC = ceil(2^63/Mc); B = (M*MAGIC) >> (177-e)
// for e in [114,129]; else 0.   (rel_err == 0, bit-exact)
//
// R11 = R7 structure with 256-bit stores (st.global.cs.v8.f32, sm_100+):
// warp owns 32 rows; lane computes its row's B once; the warp's 512 output
// floats are written as 2 fully-coalesced 1024B store instructions (each
// lane writes 8 consecutive floats = half a row). Halves store-instruction
// and shuffle counts vs R7. Data volume unchanged (DRAM-write-bound at
// ~7.2 TB/s effective; this probes residual per-instruction L1 overhead).

namespace {
constexpr float              CF    = 6.28318530717958647692f;  // fl32(2*pi) = Mc*2^-21
constexpr unsigned           MC    = 13176795u;
constexpr unsigned long long MAGIC = (0x8000000000000000ULL + (MC - 1)) / MC;
}

__device__ __forceinline__ float sgn_step(unsigned& bs) {
    float f = __uint_as_float((bs & 0x80000000u) | 0x3F800000u);
    bs += bs;
    return f;
}

__global__ void __launch_bounds__(256)
Encoder_22668837388855_kernel(const float* __restrict__ x,
                              float* __restrict__ out,
                              unsigned n) {
    unsigned lane    = threadIdx.x & 31u;
    unsigned warpGid = (blockIdx.x * blockDim.x + threadIdx.x) >> 5;
    unsigned rowBase = warpGid << 5;            // 32 rows per warp
    if (rowBase >= n) return;                   // n % 32 == 0: whole-warp guard

    float xv = __ldg(&x[rowBase + lane]);       // coalesced 128B
    float t  = __fmul_rn(CF, xv);               // fl(2pi * x)

    unsigned tb = __float_as_uint(t);
    unsigned e  = tb >> 23;
    unsigned M  = (tb & 0x7FFFFFu) | 0x800000u;
    unsigned long long P = (unsigned long long)M * MAGIC;
    unsigned B = (e >= 114u) ? (unsigned)(P >> (177u - e)) : 0u;  // exact floor(u*2^15)

    // Warp emits 512 floats as 2 x st.global.v8.f32 (1024B per instruction).
    // Store j, lane L writes floats [rowBase*16 + j*256 + 8L, +8), i.e. the
    // h-th half (h = L&1) of source row sr = j*16 + L/2.
    unsigned h      = lane & 1u;                // half of the row (cols 8h..8h+7)
    unsigned srBase = lane >> 1;
    unsigned sh     = 16u + (h << 5 >> 2);      // 16 + 8h*? -> cols 8h: shift 16+4*(2h*... )
    // col c (c>=1) sign s_{c-1} at bit (15-c) of B; first col of this half is 8h.
    // bs = B << (16 + 4*w) with w = 2h (word granularity 4 cols): for 8 cols use w=2h.
    sh = 16u + (h << 3);                        // 16 + 8h

    size_t outBase = (size_t)rowBase * 16 + (lane << 3);

#pragma unroll
    for (unsigned j = 0; j < 2; j++) {
        unsigned sr = srBase + (j << 4);
        unsigned Bs = __shfl_sync(0xFFFFFFFFu, B,  sr);
        float    xs = __shfl_sync(0xFFFFFFFFu, xv, sr);

        unsigned bs = Bs << sh;
        float f0 = sgn_step(bs), f1 = sgn_step(bs), f2 = sgn_step(bs), f3 = sgn_step(bs);
        float f4 = sgn_step(bs), f5 = sgn_step(bs), f6 = sgn_step(bs), f7 = sgn_step(bs);
        if (h == 0) f0 = xs;                    // col 0 of each row is raw x

        float* p = out + outBase + (size_t)(j << 8);
        asm volatile(
            "st.global.cs.v8.f32 [%0], {%1, %2, %3, %4, %5, %6, %7, %8};"
            :: "l"(p), "f"(f0), "f"(f1), "f"(f2), "f"(f3),
               "f"(f4), "f"(f5), "f"(f6), "f"(f7)
            : "memory");
    }
}

extern "C" void kernel_launch(void* const* d_in, const int* in_sizes, int n_in,
                              void* d_out, int out_size) {
    const float* x = (const float*)d_in[0];
    float* out = (float*)d_out;
    unsigned n = (unsigned)in_sizes[0];
    unsigned warps  = (n + 31u) / 32u;
    unsigned total  = warps * 32u;
    int threads = 256;
    unsigned blocks = (total + threads - 1) / threads;
    Encoder_22668837388855_kernel<<<blocks, threads>>>(x, out, n);
}

// round 12
// speedup vs baseline: 1.1550x; 1.1550x over previous
#include <cuda_runtime.h>
#include <cstdint>

// Encoder: out[r,0] = x[r]; out[r,1+i] = square(2*pi * x[r] * 2^i), i = 0..14
//
// Exact integer decision: with t = fl32(2pi*x) = M*2^(e-150) and
// C = fl32(2pi) = Mc*2^-21 (Mc = 13176795), sign for freq i is bit (14-i) of
//   B = floor((t/C) * 2^15) = floor(M * 2^(e-114) / Mc)
// computed exactly via Granlund-Montgomery invariant division:
//   MAGIC = ceil(2^63/Mc);  B = (M*MAGIC) >> (177-e) for e in [114,129]; else 0.
// Bit-exact vs the reference (rel_err == 0).
//
// FINAL FORM (= R7, best: 39.4us = 7.2 TB/s effective, ~90% of HBM spec).
// Falsified alternatives, all leaving profiled duration/memory counters
// unchanged at ~43us / DRAM 66%: no-shuffle recompute (R8), smem +
// cp.async.bulk stores (R9), st.global.v8.f32 256-bit stores (R11).
// The kernel is purely bound by the 284MB write-dominated stream.
//
// Structure: each warp owns 32 rows. Lane L computes row rowBase+L's 15-bit
// decision word B ONCE (coalesced 128B LDG of x), then the warp's 128 output
// float4 words are written as 4 perfectly coalesced STG.128s (4 independent
// stores in flight), each lane pulling its source row's (B, x) via shuffle.

namespace {
constexpr float              CF    = 6.28318530717958647692f;  // fl32(2*pi) = Mc*2^-21
constexpr unsigned           MC    = 13176795u;
constexpr unsigned long long MAGIC = (0x8000000000000000ULL + (MC - 1)) / MC;
}

__global__ void __launch_bounds__(256)
Encoder_22668837388855_kernel(const float* __restrict__ x,
                              float4* __restrict__ out4,
                              unsigned n) {
    unsigned lane    = threadIdx.x & 31u;
    unsigned warpGid = (blockIdx.x * blockDim.x + threadIdx.x) >> 5;
    unsigned rowBase = warpGid << 5;            // 32 rows per warp
    if (rowBase >= n) return;                   // n % 32 == 0: whole-warp guard

    float xv = __ldg(&x[rowBase + lane]);       // coalesced 128B
    float t  = __fmul_rn(CF, xv);               // fl(2pi * x)

    unsigned tb = __float_as_uint(t);
    unsigned e  = tb >> 23;
    unsigned M  = (tb & 0x7FFFFFu) | 0x800000u;
    unsigned long long P = (unsigned long long)M * MAGIC;
    unsigned B = (e >= 114u) ? (unsigned)(P >> (177u - e)) : 0u;  // exact floor(u*2^15)

    // Emit 128 words (32 rows x 4 float4) as 4 coalesced STG.128s.
    // Store j, lane L writes word rowBase*4 + j*32 + L == row (j*8 + L/4),
    // word w = L & 3 of that row.
    unsigned srBase = lane >> 2;
    unsigned w      = lane & 3u;
    unsigned sh     = 16u + (w << 2);           // word's first sign slot -> bit 31

    size_t outBase = (size_t)rowBase * 4 + lane;

#pragma unroll
    for (unsigned j = 0; j < 4; j++) {
        unsigned sr = srBase + (j << 3);
        unsigned Bs = __shfl_sync(0xFFFFFFFFu, B,  sr);
        float    xs = __shfl_sync(0xFFFFFFFFu, xv, sr);

        unsigned bs = Bs << sh;
        float4 o;
        o.x = __uint_as_float((bs & 0x80000000u) | 0x3F800000u); bs += bs;
        o.y = __uint_as_float((bs & 0x80000000u) | 0x3F800000u); bs += bs;
        o.z = __uint_as_float((bs & 0x80000000u) | 0x3F800000u); bs += bs;
        o.w = __uint_as_float((bs & 0x80000000u) | 0x3F800000u);
        if (w == 0) o.x = xs;                   // col 0 of each row is raw x

        __stcs(&out4[outBase + (size_t)(j << 5)], o);
    }
}

extern "C" void kernel_launch(void* const* d_in, const int* in_sizes, int n_in,
                              void* d_out, int out_size) {
    const float* x = (const float*)d_in[0];
    float4* out = (float4*)d_out;
    unsigned n = (unsigned)in_sizes[0];
    unsigned warps  = (n + 31u) / 32u;
    unsigned total  = warps * 32u;
    int threads = 256;
    unsigned blocks = (total + threads - 1) / threads;
    Encoder_22668837388855_kernel<<<blocks, threads>>>(x, out, n);
}